// round 15
// baseline (speedup 1.0000x reference)
#include <cuda_runtime.h>
#include <cuda_fp16.h>
#include <math.h>
#include <stdint.h>

#define N_NODES 100000
#define N_EDGES 1600000
#define D_FEAT  64
#define EPS     1e-7f
#define FULL    0xffffffffu

// Scratch
__device__ float   g_inv[N_NODES];            // 1 / ||x_i||
__device__ int     g_col[N_EDGES];            // edge_col as int32
__device__ int     g_rowptr[N_NODES + 1];
__device__ __half2 g_xh[N_NODES * 32];        // x as fp16, 128B per row

// ---------------------------------------------------------------------------
__device__ __forceinline__ int detect_is64(const unsigned int* ec_raw)
{
    unsigned acc = 0;
    #pragma unroll
    for (int i = 1; i < 16; i += 2) acc |= ec_raw[i];
    return acc == 0u;
}

__device__ __forceinline__ int get_idx(const void* p, int e, int is64)
{
    if (is64) return (int)((const long long*)p)[e];
    return ((const int*)p)[e];
}

// ---------------------------------------------------------------------------
// Prep kernel: four jobs via block-range split.
//   [0, B_NORM)       inverse norms (half-warp per node)
//   [.., +B_COL)      edge_col -> int32
//   [.., +B_ROW)      CSR row pointers (binary search over sorted edge_row)
//   [.., +B_XH)       x -> fp16 copy (each thread converts 8 floats)
// ---------------------------------------------------------------------------
#define B_NORM 6250     // N_NODES*16 / 256
#define B_COL  6250     // N_EDGES / 256
#define B_ROW  391      // ceil((N_NODES+1)/256)
#define B_XH   3125     // N_NODES*64 / (256*8)

__global__ void __launch_bounds__(256)
prep_kernel(const float4* __restrict__ x4,
            const void* __restrict__ er,
            const void* __restrict__ ec)
{
    int b = blockIdx.x;
    if (b < B_NORM) {
        int t    = b * 256 + threadIdx.x;
        int node = t >> 4;
        int sub  = t & 15;
        if (node >= N_NODES) return;
        float4 a = x4[node * 16 + sub];
        float s = a.x * a.x + a.y * a.y + a.z * a.z + a.w * a.w;
        #pragma unroll
        for (int o = 8; o; o >>= 1) s += __shfl_xor_sync(FULL, s, o);
        if (sub == 0) g_inv[node] = rsqrtf(s);
    } else if (b < B_NORM + B_COL) {
        int e = (b - B_NORM) * 256 + threadIdx.x;
        if (e >= N_EDGES) return;
        int is64 = detect_is64((const unsigned int*)ec);
        g_col[e] = get_idx(ec, e, is64);
    } else if (b < B_NORM + B_COL + B_ROW) {
        int i = (b - B_NORM - B_COL) * 256 + threadIdx.x;
        if (i > N_NODES) return;
        int is64 = detect_is64((const unsigned int*)ec);
        int lo = 0, hi = N_EDGES;
        while (lo < hi) {
            int mid = (lo + hi) >> 1;
            if (get_idx(er, mid, is64) < i) lo = mid + 1; else hi = mid;
        }
        g_rowptr[i] = lo;
    } else {
        // fp16 conversion: thread t handles floats [8t, 8t+8)
        int t = (b - B_NORM - B_COL - B_ROW) * 256 + threadIdx.x;
        if (t >= N_NODES * D_FEAT / 8) return;
        float4 a = x4[t * 2];
        float4 c = x4[t * 2 + 1];
        __half2* dst = &g_xh[t * 4];
        dst[0] = __floats2half2_rn(a.x, a.y);
        dst[1] = __floats2half2_rn(a.z, a.w);
        dst[2] = __floats2half2_rn(c.x, c.y);
        dst[3] = __floats2half2_rn(c.z, c.w);
    }
}

// ---------------------------------------------------------------------------
// Fused sim + softmax + SPMM. ONE WARP PER ROW (R6 layout).
// Lane = (group g 0..3) x (feature f 0..7): 4 edges per iteration. Neighbor
// rows gathered as fp16: ONE 16B load per lane per edge (128B/edge, single
// L1 wavefront). Converted to fp32; dot/acc fully fp32; xr is exact fp32.
// w = exp(beta*(cos-1)): shift-invariant softmax, arg<=0, no running max.
// ---------------------------------------------------------------------------
__global__ void __launch_bounds__(256)
fused_row_kernel(const float4* __restrict__ x4,
                 const float* __restrict__ beta,
                 float4* __restrict__ out4)
{
    int warp = (blockIdx.x * blockDim.x + threadIdx.x) >> 5;
    if (warp >= N_NODES) return;
    int lane = threadIdx.x & 31;
    int g = lane >> 3;                    // edge slot within iteration
    int f = lane & 7;                     // feature slice (16B of fp16 row)

    int row = warp;
    int s = g_rowptr[row];
    int n = g_rowptr[row + 1] - s;

    // xr: 8 fp32 features for this lane (floats [8f, 8f+8))
    float4 xr0 = x4[row * 16 + 2 * f];
    float4 xr1 = x4[row * 16 + 2 * f + 1];
    float  bv  = beta[0];
    float  bs  = bv * g_inv[row];         // beta / ||x_r||

    float4 acc0 = make_float4(0.f, 0.f, 0.f, 0.f);
    float4 acc1 = make_float4(0.f, 0.f, 0.f, 0.f);
    float  wsum = 0.f;

    const int* __restrict__ col = g_col;
    const uint4* __restrict__ xh = (const uint4*)g_xh;   // 8 uint4 per row

    for (int base = 0; base < n; base += 32) {
        int rem = n - base;
        int cnt = rem < 32 ? rem : 32;

        // cooperative prefetch of up to 32 indices + inverse norms
        int   myc   = (lane < cnt) ? col[s + base + lane] : row;
        float myinv = g_inv[myc];
        int iters = (cnt + 3) >> 2;

        #pragma unroll 2
        for (int it = 0; it < iters; ++it) {
            int   src   = it * 4 + g;
            int   c     = __shfl_sync(FULL, myc, src);
            float invnc = __shfl_sync(FULL, myinv, src);
            bool  valid = src < cnt;

            uint4 raw = xh[c * 8 + f];               // 8 halves
            const __half2* hp = (const __half2*)&raw;
            float2 p0 = __half22float2(hp[0]);
            float2 p1 = __half22float2(hp[1]);
            float2 p2 = __half22float2(hp[2]);
            float2 p3 = __half22float2(hp[3]);

            float d = p0.x * xr0.x + p0.y * xr0.y + p1.x * xr0.z + p1.y * xr0.w
                    + p2.x * xr1.x + p2.y * xr1.y + p3.x * xr1.z + p3.y * xr1.w;
            d += __shfl_xor_sync(FULL, d, 1);
            d += __shfl_xor_sync(FULL, d, 2);
            d += __shfl_xor_sync(FULL, d, 4);

            float w = __expf(fmaf(bs * invnc, d, -bv));  // exp(beta*(cos-1))
            w = valid ? w : 0.f;

            wsum  += w;
            acc0.x = fmaf(w, p0.x, acc0.x);
            acc0.y = fmaf(w, p0.y, acc0.y);
            acc0.z = fmaf(w, p1.x, acc0.z);
            acc0.w = fmaf(w, p1.y, acc0.w);
            acc1.x = fmaf(w, p2.x, acc1.x);
            acc1.y = fmaf(w, p2.y, acc1.y);
            acc1.z = fmaf(w, p3.x, acc1.z);
            acc1.w = fmaf(w, p3.y, acc1.w);
        }
    }

    // reduce the 4 edge-groups (butterfly -> all lanes hold totals)
    #pragma unroll
    for (int o = 8; o <= 16; o <<= 1) {
        acc0.x += __shfl_xor_sync(FULL, acc0.x, o);
        acc0.y += __shfl_xor_sync(FULL, acc0.y, o);
        acc0.z += __shfl_xor_sync(FULL, acc0.z, o);
        acc0.w += __shfl_xor_sync(FULL, acc0.w, o);
        acc1.x += __shfl_xor_sync(FULL, acc1.x, o);
        acc1.y += __shfl_xor_sync(FULL, acc1.y, o);
        acc1.z += __shfl_xor_sync(FULL, acc1.z, o);
        acc1.w += __shfl_xor_sync(FULL, acc1.w, o);
        wsum   += __shfl_xor_sync(FULL, wsum,   o);
    }

    if (g == 0) {
        float invw = (n > 0) ? (1.f / wsum) : 0.f;
        // lane f owns floats [8f, 8f+8): two contiguous float4 stores
        out4[row * 16 + 2 * f]     = make_float4(acc0.x * invw, acc0.y * invw,
                                                 acc0.z * invw, acc0.w * invw);
        out4[row * 16 + 2 * f + 1] = make_float4(acc1.x * invw, acc1.y * invw,
                                                 acc1.z * invw, acc1.w * invw);
    }
}

// ---------------------------------------------------------------------------
extern "C" void kernel_launch(void* const* d_in, const int* in_sizes, int n_in,
                              void* d_out, int out_size)
{
    const float4* x    = 0;
    const float*  beta = 0;
    const void*   er   = 0;
    const void*   ec   = 0;
    for (int i = 0; i < n_in; ++i) {
        long long sz = in_sizes[i];
        if (sz == (long long)N_NODES * D_FEAT) x = (const float4*)d_in[i];
        else if (sz == 1)                      beta = (const float*)d_in[i];
        else if (sz == N_EDGES) {
            if (!er) er = d_in[i]; else ec = d_in[i];
        }
    }
    float4* out = (float4*)d_out;

    prep_kernel<<<B_NORM + B_COL + B_ROW + B_XH, 256>>>(x, er, ec);

    {   // one warp per row
        long long total = (long long)N_NODES * 32;
        int blocks = (int)((total + 255) / 256);
        fused_row_kernel<<<blocks, 256>>>(x, beta, out);
    }
}

// round 16
// speedup vs baseline: 1.1358x; 1.1358x over previous
#include <cuda_runtime.h>
#include <math.h>
#include <stdint.h>

#define N_NODES 100000
#define N_EDGES 1600000
#define D_FEAT  64
#define EPS     1e-7f
#define FULL    0xffffffffu

// Scratch
__device__ float g_inv[N_NODES];          // 1 / ||x_i||
__device__ int   g_rowptr[N_NODES + 1];
__device__ int   g_is64;                  // 1 if edge indices are int64

// ---------------------------------------------------------------------------
__device__ __forceinline__ int get_idx(const void* p, int e, int is64)
{
    if (is64) return (int)((const long long*)p)[e];
    return ((const int*)p)[e];
}

// ---------------------------------------------------------------------------
// Kernel 0: detect index dtype (edge values random in [0,N_NODES); int64 ->
// all high 32-bit words zero).
// ---------------------------------------------------------------------------
__global__ void detect_kernel(const unsigned int* __restrict__ ec_raw)
{
    if (threadIdx.x == 0) {
        unsigned acc = 0;
        #pragma unroll
        for (int i = 1; i < 64; i += 2) acc |= ec_raw[i];
        g_is64 = (acc == 0u) ? 1 : 0;
    }
}

// ---------------------------------------------------------------------------
// Prep kernel: inverse norms + CSR row pointers (block-range split).
// ---------------------------------------------------------------------------
#define B_NORM 6250     // N_NODES*16 / 256
#define B_ROW  391      // ceil((N_NODES+1)/256)

__global__ void __launch_bounds__(256)
prep_kernel(const float4* __restrict__ x4, const void* __restrict__ er)
{
    int b = blockIdx.x;
    if (b < B_NORM) {
        int t    = b * 256 + threadIdx.x;
        int node = t >> 4;
        int sub  = t & 15;
        if (node >= N_NODES) return;
        float4 a = x4[node * 16 + sub];
        float s = a.x * a.x + a.y * a.y + a.z * a.z + a.w * a.w;
        #pragma unroll
        for (int o = 8; o; o >>= 1) s += __shfl_xor_sync(FULL, s, o);
        if (sub == 0) g_inv[node] = rsqrtf(s);
    } else {
        int i = (b - B_NORM) * 256 + threadIdx.x;
        if (i > N_NODES) return;
        int is64 = g_is64;
        int lo = 0, hi = N_EDGES;
        while (lo < hi) {
            int mid = (lo + hi) >> 1;
            if (get_idx(er, mid, is64) < i) lo = mid + 1; else hi = mid;
        }
        g_rowptr[i] = lo;
    }
}

// ---------------------------------------------------------------------------
// Fused sim + softmax + SPMM. PERSISTENT WARPS, static row striding.
// 444 blocks x 8 warps = 3552 warps, all resident (3 blocks/SM at 64 regs);
// warp w handles rows w, w+3552, ... (~28 rows each -> sums concentrate,
// no block-max inflation, no wave tail).
// Per row: R6 economy. Lane = (group g 0..3) x (feature f 0..7); 4 edges per
// iteration, each edge row = 8 lanes x two float4 (two 128B lines).
// w = exp(beta*(cos-1)): shift-invariant softmax, arg<=0, no running max.
// ---------------------------------------------------------------------------
#define N_BLOCKS 444
#define N_WARPS  (N_BLOCKS * 8)

__global__ void __launch_bounds__(256)
fused_row_kernel(const float4* __restrict__ x4,
                 const void* __restrict__ ec,
                 const float* __restrict__ beta,
                 float4* __restrict__ out4)
{
    int gw   = (blockIdx.x * blockDim.x + threadIdx.x) >> 5;
    int lane = threadIdx.x & 31;
    int g = lane >> 3;                    // edge slot within iteration
    int f = lane & 7;                     // feature slice

    int   is64 = g_is64;
    float bv   = beta[0];
    const long long* __restrict__ ec64 = (const long long*)ec;
    const int*       __restrict__ ec32 = (const int*)ec;

    for (int row = gw; row < N_NODES; row += N_WARPS) {
        int s = g_rowptr[row];
        int n = g_rowptr[row + 1] - s;

        float4 xr0 = x4[row * 16 + f];
        float4 xr1 = x4[row * 16 + 8 + f];
        float  bs  = bv * g_inv[row];     // beta / ||x_r||

        float4 acc0 = make_float4(0.f, 0.f, 0.f, 0.f);
        float4 acc1 = make_float4(0.f, 0.f, 0.f, 0.f);
        float  wsum = 0.f;

        for (int base = 0; base < n; base += 32) {
            int rem = n - base;
            int cnt = rem < 32 ? rem : 32;

            // cooperative prefetch of up to 32 indices + inverse norms
            int myc = row;
            if (lane < cnt) {
                int e = s + base + lane;
                myc = is64 ? (int)ec64[e] : ec32[e];
            }
            float myinv = g_inv[myc];
            int iters = (cnt + 3) >> 2;

            #pragma unroll 2
            for (int it = 0; it < iters; ++it) {
                int   src   = it * 4 + g;
                int   c     = __shfl_sync(FULL, myc, src);
                float invnc = __shfl_sync(FULL, myinv, src);
                bool  valid = src < cnt;

                float4 b0 = x4[c * 16 + f];
                float4 b1 = x4[c * 16 + 8 + f];

                float d = b0.x * xr0.x + b0.y * xr0.y + b0.z * xr0.z + b0.w * xr0.w
                        + b1.x * xr1.x + b1.y * xr1.y + b1.z * xr1.z + b1.w * xr1.w;
                d += __shfl_xor_sync(FULL, d, 1);
                d += __shfl_xor_sync(FULL, d, 2);
                d += __shfl_xor_sync(FULL, d, 4);

                float w = __expf(fmaf(bs * invnc, d, -bv));  // exp(beta*(cos-1))
                w = valid ? w : 0.f;

                wsum  += w;
                acc0.x = fmaf(w, b0.x, acc0.x);
                acc0.y = fmaf(w, b0.y, acc0.y);
                acc0.z = fmaf(w, b0.z, acc0.z);
                acc0.w = fmaf(w, b0.w, acc0.w);
                acc1.x = fmaf(w, b1.x, acc1.x);
                acc1.y = fmaf(w, b1.y, acc1.y);
                acc1.z = fmaf(w, b1.z, acc1.z);
                acc1.w = fmaf(w, b1.w, acc1.w);
            }
        }

        // reduce the 4 edge-groups (butterfly -> all lanes hold totals)
        #pragma unroll
        for (int o = 8; o <= 16; o <<= 1) {
            acc0.x += __shfl_xor_sync(FULL, acc0.x, o);
            acc0.y += __shfl_xor_sync(FULL, acc0.y, o);
            acc0.z += __shfl_xor_sync(FULL, acc0.z, o);
            acc0.w += __shfl_xor_sync(FULL, acc0.w, o);
            acc1.x += __shfl_xor_sync(FULL, acc1.x, o);
            acc1.y += __shfl_xor_sync(FULL, acc1.y, o);
            acc1.z += __shfl_xor_sync(FULL, acc1.z, o);
            acc1.w += __shfl_xor_sync(FULL, acc1.w, o);
            wsum   += __shfl_xor_sync(FULL, wsum,   o);
        }

        if (g == 0) {
            float invw = (n > 0) ? (1.f / wsum) : 0.f;
            out4[row * 16 + f]     = make_float4(acc0.x * invw, acc0.y * invw,
                                                 acc0.z * invw, acc0.w * invw);
            out4[row * 16 + 8 + f] = make_float4(acc1.x * invw, acc1.y * invw,
                                                 acc1.z * invw, acc1.w * invw);
        }
    }
}

// ---------------------------------------------------------------------------
extern "C" void kernel_launch(void* const* d_in, const int* in_sizes, int n_in,
                              void* d_out, int out_size)
{
    const float4* x    = 0;
    const float*  beta = 0;
    const void*   er   = 0;
    const void*   ec   = 0;
    for (int i = 0; i < n_in; ++i) {
        long long sz = in_sizes[i];
        if (sz == (long long)N_NODES * D_FEAT) x = (const float4*)d_in[i];
        else if (sz == 1)                      beta = (const float*)d_in[i];
        else if (sz == N_EDGES) {
            if (!er) er = d_in[i]; else ec = d_in[i];
        }
    }
    float4* out = (float4*)d_out;

    detect_kernel<<<1, 32>>>((const unsigned int*)ec);
    prep_kernel<<<B_NORM + B_ROW, 256>>>(x, er);
    fused_row_kernel<<<N_BLOCKS, 256>>>(x, ec, beta, out);
}

// round 17
// speedup vs baseline: 1.1645x; 1.0253x over previous
#include <cuda_runtime.h>
#include <math.h>
#include <stdint.h>

#define N_NODES 100000
#define N_EDGES 1600000
#define D_FEAT  64
#define EPS     1e-7f
#define FULL    0xffffffffu

// Scratch
__device__ float g_inv[N_NODES];          // 1 / ||x_i||
__device__ int   g_rowptr[N_NODES + 1];
__device__ int   g_is64;                  // published by prep for fused

// ---------------------------------------------------------------------------
// Local dtype detection: edge values are random in [0, N_NODES); if int64,
// all high 32-bit words are zero. 32 odd words -> P(false positive) ~ 0.
// ---------------------------------------------------------------------------
__device__ __forceinline__ int detect_is64_local(const unsigned int* ec_raw)
{
    unsigned acc = 0;
    #pragma unroll
    for (int i = 1; i < 64; i += 2) acc |= ec_raw[i];
    return acc == 0u;
}

__device__ __forceinline__ int get_idx(const void* p, int e, int is64)
{
    if (is64) return (int)((const long long*)p)[e];
    return ((const int*)p)[e];
}

// ---------------------------------------------------------------------------
// Prep kernel: inverse norms + CSR row pointers (block-range split).
// Rowptr blocks detect the index dtype locally (no separate launch); one
// thread publishes g_is64 for the subsequent fused kernel.
// ---------------------------------------------------------------------------
#define B_NORM 6250     // N_NODES*16 / 256
#define B_ROW  391      // ceil((N_NODES+1)/256)

__global__ void __launch_bounds__(256)
prep_kernel(const float4* __restrict__ x4,
            const void* __restrict__ er,
            const void* __restrict__ ec)
{
    int b = blockIdx.x;
    if (b < B_NORM) {
        int t    = b * 256 + threadIdx.x;
        int node = t >> 4;
        int sub  = t & 15;
        if (node >= N_NODES) return;
        float4 a = x4[node * 16 + sub];
        float s = a.x * a.x + a.y * a.y + a.z * a.z + a.w * a.w;
        #pragma unroll
        for (int o = 8; o; o >>= 1) s += __shfl_xor_sync(FULL, s, o);
        if (sub == 0) g_inv[node] = rsqrtf(s);
    } else {
        // local detection (cheap; L2-resident after first block touches it)
        int is64 = detect_is64_local((const unsigned int*)ec);
        if (b == B_NORM && threadIdx.x == 0) g_is64 = is64;  // publish

        int i = (b - B_NORM) * 256 + threadIdx.x;
        if (i > N_NODES) return;
        int lo = 0, hi = N_EDGES;
        while (lo < hi) {
            int mid = (lo + hi) >> 1;
            if (get_idx(er, mid, is64) < i) lo = mid + 1; else hi = mid;
        }
        g_rowptr[i] = lo;
    }
}

// ---------------------------------------------------------------------------
// Fused sim + softmax + SPMM. PERSISTENT WARPS, static row striding.
// 444 blocks x 8 warps = 3552 warps, all resident (3 blocks/SM at 64 regs);
// warp w handles rows w, w+3552, ... (~28 rows each -> per-warp work sums
// concentrate: no block-max inflation, no wave tail).
// Per row: lane = (group g 0..3) x (feature f 0..7); 4 edges per iteration,
// each edge row = 8 lanes x two float4 (two 128B lines). Chunk-32 index
// prefetch + shuffle broadcast. w = exp(beta*(cos-1)): shift-invariant
// softmax, arg <= 0, no running max.
// ---------------------------------------------------------------------------
#define N_BLOCKS 444
#define N_WARPS  (N_BLOCKS * 8)

__global__ void __launch_bounds__(256)
fused_row_kernel(const float4* __restrict__ x4,
                 const void* __restrict__ ec,
                 const float* __restrict__ beta,
                 float4* __restrict__ out4)
{
    int gw   = (blockIdx.x * blockDim.x + threadIdx.x) >> 5;
    int lane = threadIdx.x & 31;
    int g = lane >> 3;                    // edge slot within iteration
    int f = lane & 7;                     // feature slice

    int   is64 = g_is64;
    float bv   = beta[0];
    const long long* __restrict__ ec64 = (const long long*)ec;
    const int*       __restrict__ ec32 = (const int*)ec;

    for (int row = gw; row < N_NODES; row += N_WARPS) {
        int s = g_rowptr[row];
        int n = g_rowptr[row + 1] - s;

        float4 xr0 = x4[row * 16 + f];
        float4 xr1 = x4[row * 16 + 8 + f];
        float  bs  = bv * g_inv[row];     // beta / ||x_r||

        float4 acc0 = make_float4(0.f, 0.f, 0.f, 0.f);
        float4 acc1 = make_float4(0.f, 0.f, 0.f, 0.f);
        float  wsum = 0.f;

        for (int base = 0; base < n; base += 32) {
            int rem = n - base;
            int cnt = rem < 32 ? rem : 32;

            // cooperative prefetch of up to 32 indices + inverse norms
            int myc = row;
            if (lane < cnt) {
                int e = s + base + lane;
                myc = is64 ? (int)ec64[e] : ec32[e];
            }
            float myinv = g_inv[myc];
            int iters = (cnt + 3) >> 2;

            #pragma unroll 2
            for (int it = 0; it < iters; ++it) {
                int   src   = it * 4 + g;
                int   c     = __shfl_sync(FULL, myc, src);
                float invnc = __shfl_sync(FULL, myinv, src);
                bool  valid = src < cnt;

                float4 b0 = x4[c * 16 + f];
                float4 b1 = x4[c * 16 + 8 + f];

                float d = b0.x * xr0.x + b0.y * xr0.y + b0.z * xr0.z + b0.w * xr0.w
                        + b1.x * xr1.x + b1.y * xr1.y + b1.z * xr1.z + b1.w * xr1.w;
                d += __shfl_xor_sync(FULL, d, 1);
                d += __shfl_xor_sync(FULL, d, 2);
                d += __shfl_xor_sync(FULL, d, 4);

                float w = __expf(fmaf(bs * invnc, d, -bv));  // exp(beta*(cos-1))
                w = valid ? w : 0.f;

                wsum  += w;
                acc0.x = fmaf(w, b0.x, acc0.x);
                acc0.y = fmaf(w, b0.y, acc0.y);
                acc0.z = fmaf(w, b0.z, acc0.z);
                acc0.w = fmaf(w, b0.w, acc0.w);
                acc1.x = fmaf(w, b1.x, acc1.x);
                acc1.y = fmaf(w, b1.y, acc1.y);
                acc1.z = fmaf(w, b1.z, acc1.z);
                acc1.w = fmaf(w, b1.w, acc1.w);
            }
        }

        // reduce the 4 edge-groups (butterfly -> all lanes hold totals)
        #pragma unroll
        for (int o = 8; o <= 16; o <<= 1) {
            acc0.x += __shfl_xor_sync(FULL, acc0.x, o);
            acc0.y += __shfl_xor_sync(FULL, acc0.y, o);
            acc0.z += __shfl_xor_sync(FULL, acc0.z, o);
            acc0.w += __shfl_xor_sync(FULL, acc0.w, o);
            acc1.x += __shfl_xor_sync(FULL, acc1.x, o);
            acc1.y += __shfl_xor_sync(FULL, acc1.y, o);
            acc1.z += __shfl_xor_sync(FULL, acc1.z, o);
            acc1.w += __shfl_xor_sync(FULL, acc1.w, o);
            wsum   += __shfl_xor_sync(FULL, wsum,   o);
        }

        if (g == 0) {
            float invw = (n > 0) ? (1.f / wsum) : 0.f;
            out4[row * 16 + f]     = make_float4(acc0.x * invw, acc0.y * invw,
                                                 acc0.z * invw, acc0.w * invw);
            out4[row * 16 + 8 + f] = make_float4(acc1.x * invw, acc1.y * invw,
                                                 acc1.z * invw, acc1.w * invw);
        }
    }
}

// ---------------------------------------------------------------------------
extern "C" void kernel_launch(void* const* d_in, const int* in_sizes, int n_in,
                              void* d_out, int out_size)
{
    const float4* x    = 0;
    const float*  beta = 0;
    const void*   er   = 0;
    const void*   ec   = 0;
    for (int i = 0; i < n_in; ++i) {
        long long sz = in_sizes[i];
        if (sz == (long long)N_NODES * D_FEAT) x = (const float4*)d_in[i];
        else if (sz == 1)                      beta = (const float*)d_in[i];
        else if (sz == N_EDGES) {
            if (!er) er = d_in[i]; else ec = d_in[i];
        }
    }
    float4* out = (float4*)d_out;

    prep_kernel<<<B_NORM + B_ROW, 256>>>(x, er, ec);
    fused_row_kernel<<<N_BLOCKS, 256>>>(x, ec, beta, out);
}